// round 8
// baseline (speedup 1.0000x reference)
#include <cuda_runtime.h>
#include <cuda_bf16.h>
#include <cstdint>

#define BB 32
#define DD 640
#define MM 1024
#define TRI (DD*(DD+1)/2)
#define TEMPR (1.0f/(2.0f*DD*MM))
#define EPSV 1e-5f

#define NBL 5                 /* 640/128 tile blocks per dim */
#define NTILE (NBL*(NBL+1)/2) /* 15 upper-tri tiles */
#define KC 32                 /* bf16 K per chunk; hi|lo packed -> 128B/row */
#define NCH (MM/KC)           /* 32 chunks */

// ---- device scratch (no runtime allocation) ----
// g_hl row layout: per source row, 32 chunks of [hi x32 bf16 | lo x32 bf16]
__device__ __align__(256) __nv_bfloat16 g_hl[(size_t)BB*DD*2048];  // 83.9 MB
__device__ __align__(256) float g_dcov[(size_t)BB*DD*DD];          // upper tiles only
__device__ float g_diag[BB*DD];
__device__ float g_rspart[(size_t)BB*NBL*DD];
__device__ float g_rowsum[BB*DD];   // pre-scaled by 1/D
__device__ float g_tot[BB];         // pre-scaled by 1/D^2

// ---------------- baseline-PTX helpers ----------------
__device__ __forceinline__ uint32_t smem_u32(const void* p) {
    uint32_t a;
    asm("{ .reg .u64 t; cvta.to.shared.u64 t, %1; cvt.u32.u64 %0, t; }" : "=r"(a) : "l"(p));
    return a;
}
#define SW128(o) ((o) ^ (((o) >> 3) & 0x70))

#define CP_ASYNC16(dst, src) \
    asm volatile("cp.async.cg.shared.global [%0], [%1], 16;" :: "r"(dst), "l"(src) : "memory")
#define CP_COMMIT() asm volatile("cp.async.commit_group;" ::: "memory")
#define CP_WAIT1()  asm volatile("cp.async.wait_group 1;" ::: "memory")
#define CP_WAIT0()  asm volatile("cp.async.wait_group 0;" ::: "memory")

#define LDSM4(r, addr) \
    asm volatile("ldmatrix.sync.aligned.m8n8.x4.shared.b16 {%0,%1,%2,%3}, [%4];" \
                 : "=r"((r)[0]), "=r"((r)[1]), "=r"((r)[2]), "=r"((r)[3]) : "r"(addr))

#define MMA_BF16(c, a, b0, b1) \
    asm volatile("mma.sync.aligned.m16n8k16.row.col.f32.bf16.bf16.f32 " \
                 "{%0,%1,%2,%3}, {%4,%5,%6,%7}, {%8,%9}, {%0,%1,%2,%3};" \
                 : "+f"((c)[0]), "+f"((c)[1]), "+f"((c)[2]), "+f"((c)[3]) \
                 : "r"((a)[0]), "r"((a)[1]), "r"((a)[2]), "r"((a)[3]), "r"(b0), "r"(b1))

// ---------------------------------------------------------------------------
// Kernel 1: fp32 -> packed (hi|lo) bf16 + diag row-norms. One warp per row.
// ---------------------------------------------------------------------------
__global__ void conv_diag_kernel(const float* __restrict__ x) {
    int w = (blockIdx.x * blockDim.x + threadIdx.x) >> 5;
    int lane = threadIdx.x & 31;
    if (w >= BB * DD) return;
    const float4* row = reinterpret_cast<const float4*>(x + (size_t)w * MM);
    __nv_bfloat16* pr = g_hl + (size_t)w * 2048;
    float s = 0.f;
    #pragma unroll
    for (int m4 = lane; m4 < MM / 4; m4 += 32) {
        float4 v = row[m4];
        s += v.x*v.x + v.y*v.y + v.z*v.z + v.w*v.w;
        __nv_bfloat16 h0 = __float2bfloat16(v.x), h1 = __float2bfloat16(v.y);
        __nv_bfloat16 h2 = __float2bfloat16(v.z), h3 = __float2bfloat16(v.w);
        __nv_bfloat16 l0 = __float2bfloat16(v.x - __bfloat162float(h0));
        __nv_bfloat16 l1 = __float2bfloat16(v.y - __bfloat162float(h1));
        __nv_bfloat16 l2 = __float2bfloat16(v.z - __bfloat162float(h2));
        __nv_bfloat16 l3 = __float2bfloat16(v.w - __bfloat162float(h3));
        uint2 hp, lp;
        hp.x = ((uint32_t)__bfloat16_as_ushort(h1) << 16) | __bfloat16_as_ushort(h0);
        hp.y = ((uint32_t)__bfloat16_as_ushort(h3) << 16) | __bfloat16_as_ushort(h2);
        lp.x = ((uint32_t)__bfloat16_as_ushort(l1) << 16) | __bfloat16_as_ushort(l0);
        lp.y = ((uint32_t)__bfloat16_as_ushort(l3) << 16) | __bfloat16_as_ushort(l2);
        int col0 = m4 * 4;
        int kc = col0 >> 5, wi = col0 & 31;
        *reinterpret_cast<uint2*>(pr + kc * 64 + wi)      = hp;
        *reinterpret_cast<uint2*>(pr + kc * 64 + 32 + wi) = lp;
    }
    #pragma unroll
    for (int o = 16; o > 0; o >>= 1) s += __shfl_down_sync(0xffffffffu, s, o);
    if (lane == 0) g_diag[w] = s;
}

// ---------------------------------------------------------------------------
// Kernel 2: Gram via mma.sync bf16 (hi/lo, 3 passes), 128x128 tiles,
// KC=32 packed hi|lo rows, 3-stage cp.async pipeline, 2 CTAs/SM.
// ---------------------------------------------------------------------------
// dyn smem: three 32KB stages (A 16K, B 16K each). Epilogue reuses as
// float stage[128][132] (67.6KB).
#define STAGE_BYTES 32768
#define SMEM_BYTES  98304

__device__ __forceinline__ void load_tile_async(const __nv_bfloat16* src,
                                                uint32_t dst, int kc, int tid) {
    #pragma unroll
    for (int it = 0; it < 4; it++) {
        int idx = it * 256 + tid;           // 0..1023
        int row = idx >> 3, c16 = idx & 7;
        const char* s = (const char*)src + (size_t)row * 4096 + kc * 128 + c16 * 16;
        uint32_t off = (uint32_t)(row * 128 + c16 * 16);
        CP_ASYNC16(dst + SW128(off), s);
    }
}

__global__ __launch_bounds__(256, 2) void gram_mma_kernel() {
    extern __shared__ __align__(1024) uint8_t smem[];
    uint32_t sb = smem_u32(smem);
    __shared__ float s_di[128], s_dj[128];

    int tid = threadIdx.x;
    int wid = tid >> 5, lane = tid & 31;
    int bb = blockIdx.y;

    int lin = blockIdx.x, ti = 0, rem = lin;
    while (rem >= NBL - ti) { rem -= NBL - ti; ti++; }
    int tj = ti + rem;
    bool isdiag = (ti == tj);
    int gi0 = ti * 128, gj0 = tj * 128;

    const __nv_bfloat16* pA = g_hl + (size_t)(bb * DD + gi0) * 2048;
    const __nv_bfloat16* pB = g_hl + (size_t)(bb * DD + gj0) * 2048;

    int wr = wid >> 2, wc = wid & 3;   // 2 x 4 warp grid; warp tile 64x32

    int a_row = lane & 15;
    int a_kb  = (lane >> 4) * 16;
    int b_row = ((lane >> 4) << 3) + (lane & 7);
    int b_kb  = ((lane >> 3) & 1) * 16;

    float acc[4][4][4];
    #pragma unroll
    for (int i = 0; i < 4; i++)
        #pragma unroll
        for (int j = 0; j < 4; j++)
            #pragma unroll
            for (int k = 0; k < 4; k++) acc[i][j][k] = 0.f;

    // preload chunks 0, 1 into stages 0, 1 (separate commit groups)
    load_tile_async(pA, sb, 0, tid);
    if (!isdiag) load_tile_async(pB, sb + 16384, 0, tid);
    CP_COMMIT();
    load_tile_async(pA, sb + STAGE_BYTES, 1, tid);
    if (!isdiag) load_tile_async(pB, sb + STAGE_BYTES + 16384, 1, tid);
    CP_COMMIT();

    int slot = 0;
    for (int kc = 0; kc < NCH; kc++) {
        uint32_t cur = sb + (uint32_t)slot * STAGE_BYTES;
        CP_WAIT1();          // chunk kc arrived (<=1 group outstanding)
        __syncthreads();     // block-wide visibility + prev compute done on slot+2
        if (kc + 2 < NCH) {
            int ns = slot + 2; if (ns >= 3) ns -= 3;
            uint32_t nxt = sb + (uint32_t)ns * STAGE_BYTES;
            load_tile_async(pA, nxt, kc + 2, tid);
            if (!isdiag) load_tile_async(pB, nxt + 16384, kc + 2, tid);
            CP_COMMIT();
        } else {
            CP_COMMIT();     // keep group count in lockstep for WAIT1 semantics
        }
        uint32_t Ab = cur;
        uint32_t Bb = isdiag ? cur : cur + 16384;
        #pragma unroll
        for (int ks = 0; ks < 2; ks++) {
            uint32_t bh[2][4], bl[2][4];
            #pragma unroll
            for (int n2 = 0; n2 < 2; n2++) {
                uint32_t off = (uint32_t)((wc * 32 + n2 * 16 + b_row) * 128 + ks * 32 + b_kb);
                LDSM4(bh[n2], Bb + SW128(off));
                LDSM4(bl[n2], Bb + SW128(off + 64));
            }
            #pragma unroll
            for (int mtg = 0; mtg < 2; mtg++) {
                uint32_t ah[2][4], al[2][4];
                #pragma unroll
                for (int m2 = 0; m2 < 2; m2++) {
                    int mt = mtg * 2 + m2;
                    uint32_t off = (uint32_t)((wr * 64 + mt * 16 + a_row) * 128 + ks * 32 + a_kb);
                    LDSM4(ah[m2], Ab + SW128(off));
                    LDSM4(al[m2], Ab + SW128(off + 64));
                }
                #pragma unroll
                for (int m2 = 0; m2 < 2; m2++) {
                    int mt = mtg * 2 + m2;
                    #pragma unroll
                    for (int nt = 0; nt < 4; nt++) {
                        int n2 = nt >> 1, hb = (nt & 1) * 2;
                        float* c = acc[mt][nt];
                        MMA_BF16(c, ah[m2], bh[n2][hb], bh[n2][hb + 1]);
                        MMA_BF16(c, ah[m2], bl[n2][hb], bl[n2][hb + 1]);
                        MMA_BF16(c, al[m2], bh[n2][hb], bh[n2][hb + 1]);
                    }
                }
            }
        }
        if (++slot >= 3) slot = 0;
    }
    CP_WAIT0();   // drain dummy groups

    // ---- epilogue: one shot through stage[128][132] ----
    if (tid < 128) {
        s_di[tid] = g_diag[bb * DD + gi0 + tid];
        s_dj[tid] = g_diag[bb * DD + gj0 + tid];
    }
    __syncthreads();   // all warps done with pipeline smem

    float* stage = reinterpret_cast<float*>(smem);   // [128][132]
    float* dcb = g_dcov + (size_t)bb * DD * DD;
    int qr = lane >> 2, qc = lane & 3;

    #pragma unroll
    for (int mt = 0; mt < 4; mt++) {
        int r0 = wr * 64 + mt * 16 + qr;
        float di0 = s_di[r0], di1 = s_di[r0 + 8];
        #pragma unroll
        for (int nt = 0; nt < 4; nt++) {
            int c0 = wc * 32 + nt * 8 + qc * 2;
            float dj0 = s_dj[c0], dj1 = s_dj[c0 + 1];
            float* c = acc[mt][nt];
            stage[r0 * 132 + c0]           = sqrtf(fmaf(TEMPR, fmaxf(di0 + dj0 - 2.f * c[0], 0.f), EPSV));
            stage[r0 * 132 + c0 + 1]       = sqrtf(fmaf(TEMPR, fmaxf(di0 + dj1 - 2.f * c[1], 0.f), EPSV));
            stage[(r0 + 8) * 132 + c0]     = sqrtf(fmaf(TEMPR, fmaxf(di1 + dj0 - 2.f * c[2], 0.f), EPSV));
            stage[(r0 + 8) * 132 + c0 + 1] = sqrtf(fmaf(TEMPR, fmaxf(di1 + dj1 - 2.f * c[3], 0.f), EPSV));
        }
    }
    __syncthreads();

    // coalesced dcov store: 128 x 128
    #pragma unroll
    for (int it = 0; it < 64; it++) {
        int idx = it * 256 + tid;
        int r = idx >> 7, cjj = idx & 127;
        dcb[(size_t)(gi0 + r) * DD + gj0 + cjj] = stage[r * 132 + cjj];
    }
    // row partial sums -> slot [tj]
    #pragma unroll
    for (int rr = 0; rr < 16; rr++) {
        int r = wid * 16 + rr;
        float s = stage[r * 132 + lane] + stage[r * 132 + lane + 32] +
                  stage[r * 132 + lane + 64] + stage[r * 132 + lane + 96];
        #pragma unroll
        for (int o = 16; o > 0; o >>= 1) s += __shfl_down_sync(0xffffffffu, s, o);
        if (lane == 0) g_rspart[((size_t)bb * NBL + tj) * DD + gi0 + r] = s;
    }
    // column partial sums (mirror), off-diagonal only
    if (!isdiag && tid < 128) {
        float s = 0.f;
        #pragma unroll 8
        for (int r = 0; r < 128; r++) s += stage[r * 132 + tid];
        g_rspart[((size_t)bb * NBL + ti) * DD + gj0 + tid] = s;
    }
}

// ---------------------------------------------------------------------------
// Kernel 3: combine partials -> rowsum/D + tot/D^2 (deterministic)
// ---------------------------------------------------------------------------
__global__ void combine_kernel() {
    int b = blockIdx.x;
    __shared__ float sh[256];
    const float inv_d = 1.f / DD;
    float loc = 0.f;
    for (int i = threadIdx.x; i < DD; i += 256) {
        float s = 0.f;
        #pragma unroll
        for (int t = 0; t < NBL; t++) s += g_rspart[((size_t)b * NBL + t) * DD + i];
        g_rowsum[b * DD + i] = s * inv_d;
        loc += s;
    }
    sh[threadIdx.x] = loc;
    __syncthreads();
    #pragma unroll
    for (int o = 128; o > 0; o >>= 1) {
        if (threadIdx.x < o) sh[threadIdx.x] += sh[threadIdx.x + o];
        __syncthreads();
    }
    if (threadIdx.x == 0) g_tot[b] = sh[0] * (inv_d * inv_d);
}

// ---------------------------------------------------------------------------
// Kernel 4: centering + triu gather, flat-index fully coalesced.
// k -> (i, j): i = floor((2D+1 - sqrt((2D+1)^2 - 8k)) / 2) with int fixup.
// ---------------------------------------------------------------------------
__global__ void out_kernel(float* __restrict__ out) {
    int k = blockIdx.x * 256 + threadIdx.x;
    int b = blockIdx.y;
    if (k >= TRI) return;
    float disc = (float)(1281 * 1281 - 8 * k);   // exact: < 2^24
    int i = (int)((1281.f - sqrtf(disc)) * 0.5f);
    // fixup (rare, +-1)
    while ((i + 1) * DD - ((i + 1) * i) / 2 <= k) i++;
    while (i * DD - (i * (i - 1)) / 2 > k) i--;
    int j = k - (i * DD - (i * (i - 1)) / 2) + i;
    float v = g_dcov[((size_t)b * DD + i) * DD + j];
    out[(size_t)b * TRI + k] = v - g_rowsum[b * DD + i] - g_rowsum[b * DD + j] + g_tot[b];
}

// ---------------------------------------------------------------------------
extern "C" void kernel_launch(void* const* d_in, const int* in_sizes, int n_in,
                              void* d_out, int out_size) {
    const float* x = (const float*)d_in[0];
    float* out = (float*)d_out;

    cudaFuncSetAttribute(gram_mma_kernel,
                         cudaFuncAttributeMaxDynamicSharedMemorySize, SMEM_BYTES);

    conv_diag_kernel<<<(BB * DD) / 8, 256>>>(x);
    gram_mma_kernel<<<dim3(NTILE, BB), 256, SMEM_BYTES>>>();
    combine_kernel<<<BB, 256>>>();
    out_kernel<<<dim3((TRI + 255) / 256, BB), 256>>>(out);
}

// round 9
// speedup vs baseline: 1.0139x; 1.0139x over previous
#include <cuda_runtime.h>
#include <cuda_bf16.h>
#include <cstdint>

#define BB 32
#define DD 640
#define MM 1024
#define TRI (DD*(DD+1)/2)
#define TEMPR (1.0f/(2.0f*DD*MM))
#define EPSV 1e-5f

#define NBL 5                 /* 640/128 tile blocks per dim */
#define NTILE (NBL*(NBL+1)/2) /* 15 upper-tri tiles */
#define NWORK (NTILE*BB)      /* 480 work units */
#define KC 32                 /* bf16 K per chunk; hi|lo packed -> 128B/row */
#define NCH (MM/KC)           /* 32 chunks */
#define GRAM_CTAS 296         /* 2 per SM x 148 SMs */

// ---- device scratch (no runtime allocation) ----
__device__ __align__(256) __nv_bfloat16 g_hl[(size_t)BB*DD*2048];  // 83.9 MB
__device__ __align__(256) float g_dcov[(size_t)BB*DD*DD];          // upper tiles only
__device__ float g_diag[BB*DD];
__device__ float g_rspart[(size_t)BB*NBL*DD];
__device__ float g_rowsum[BB*DD];   // pre-scaled by 1/D
__device__ float g_tot[BB];         // pre-scaled by 1/D^2
__device__ int   g_work;            // work-queue counter (reset by conv_diag)

// ---------------- baseline-PTX helpers ----------------
__device__ __forceinline__ uint32_t smem_u32(const void* p) {
    uint32_t a;
    asm("{ .reg .u64 t; cvta.to.shared.u64 t, %1; cvt.u32.u64 %0, t; }" : "=r"(a) : "l"(p));
    return a;
}
#define SW128(o) ((o) ^ (((o) >> 3) & 0x70))

#define CP_ASYNC16(dst, src) \
    asm volatile("cp.async.cg.shared.global [%0], [%1], 16;" :: "r"(dst), "l"(src) : "memory")
#define CP_COMMIT() asm volatile("cp.async.commit_group;" ::: "memory")
#define CP_WAIT1()  asm volatile("cp.async.wait_group 1;" ::: "memory")
#define CP_WAIT0()  asm volatile("cp.async.wait_group 0;" ::: "memory")

#define LDSM4(r, addr) \
    asm volatile("ldmatrix.sync.aligned.m8n8.x4.shared.b16 {%0,%1,%2,%3}, [%4];" \
                 : "=r"((r)[0]), "=r"((r)[1]), "=r"((r)[2]), "=r"((r)[3]) : "r"(addr))

#define MMA_BF16(c, a, b0, b1) \
    asm volatile("mma.sync.aligned.m16n8k16.row.col.f32.bf16.bf16.f32 " \
                 "{%0,%1,%2,%3}, {%4,%5,%6,%7}, {%8,%9}, {%0,%1,%2,%3};" \
                 : "+f"((c)[0]), "+f"((c)[1]), "+f"((c)[2]), "+f"((c)[3]) \
                 : "r"((a)[0]), "r"((a)[1]), "r"((a)[2]), "r"((a)[3]), "r"(b0), "r"(b1))

// ---------------------------------------------------------------------------
// Kernel 1: fp32 -> packed (hi|lo) bf16 + diag row-norms. One warp per row.
// Also resets the gram work-queue counter (stream-ordered before gram).
// ---------------------------------------------------------------------------
__global__ void conv_diag_kernel(const float* __restrict__ x) {
    if (blockIdx.x == 0 && threadIdx.x == 0) g_work = 0;
    int w = (blockIdx.x * blockDim.x + threadIdx.x) >> 5;
    int lane = threadIdx.x & 31;
    if (w >= BB * DD) return;
    const float4* row = reinterpret_cast<const float4*>(x + (size_t)w * MM);
    __nv_bfloat16* pr = g_hl + (size_t)w * 2048;
    float s = 0.f;
    #pragma unroll
    for (int m4 = lane; m4 < MM / 4; m4 += 32) {
        float4 v = row[m4];
        s += v.x*v.x + v.y*v.y + v.z*v.z + v.w*v.w;
        __nv_bfloat16 h0 = __float2bfloat16(v.x), h1 = __float2bfloat16(v.y);
        __nv_bfloat16 h2 = __float2bfloat16(v.z), h3 = __float2bfloat16(v.w);
        __nv_bfloat16 l0 = __float2bfloat16(v.x - __bfloat162float(h0));
        __nv_bfloat16 l1 = __float2bfloat16(v.y - __bfloat162float(h1));
        __nv_bfloat16 l2 = __float2bfloat16(v.z - __bfloat162float(h2));
        __nv_bfloat16 l3 = __float2bfloat16(v.w - __bfloat162float(h3));
        uint2 hp, lp;
        hp.x = ((uint32_t)__bfloat16_as_ushort(h1) << 16) | __bfloat16_as_ushort(h0);
        hp.y = ((uint32_t)__bfloat16_as_ushort(h3) << 16) | __bfloat16_as_ushort(h2);
        lp.x = ((uint32_t)__bfloat16_as_ushort(l1) << 16) | __bfloat16_as_ushort(l0);
        lp.y = ((uint32_t)__bfloat16_as_ushort(l3) << 16) | __bfloat16_as_ushort(l2);
        int col0 = m4 * 4;
        int kc = col0 >> 5, wi = col0 & 31;
        *reinterpret_cast<uint2*>(pr + kc * 64 + wi)      = hp;
        *reinterpret_cast<uint2*>(pr + kc * 64 + 32 + wi) = lp;
    }
    #pragma unroll
    for (int o = 16; o > 0; o >>= 1) s += __shfl_down_sync(0xffffffffu, s, o);
    if (lane == 0) g_diag[w] = s;
}

// ---------------------------------------------------------------------------
// Kernel 2: persistent Gram via mma.sync bf16 (hi/lo, 3 passes), 128x128
// tiles, KC=32 packed hi|lo rows, 3-stage cp.async, int work queue.
// ---------------------------------------------------------------------------
#define STAGE_BYTES 32768
#define SMEM_BYTES  98304

__device__ __forceinline__ void load_tile_async(const __nv_bfloat16* src,
                                                uint32_t dst, int kc, int tid) {
    #pragma unroll
    for (int it = 0; it < 4; it++) {
        int idx = it * 256 + tid;           // 0..1023
        int row = idx >> 3, c16 = idx & 7;
        const char* s = (const char*)src + (size_t)row * 4096 + kc * 128 + c16 * 16;
        uint32_t off = (uint32_t)(row * 128 + c16 * 16);
        CP_ASYNC16(dst + SW128(off), s);
    }
}

__global__ __launch_bounds__(256, 2) void gram_mma_kernel() {
    extern __shared__ __align__(1024) uint8_t smem[];
    uint32_t sb = smem_u32(smem);
    __shared__ float s_di[128], s_dj[128];
    __shared__ int s_w;

    int tid = threadIdx.x;
    int wid = tid >> 5, lane = tid & 31;
    int wr = wid >> 2, wc = wid & 3;   // 2 x 4 warp grid; warp tile 64x32

    int a_row = lane & 15;
    int a_kb  = (lane >> 4) * 16;
    int b_row = ((lane >> 4) << 3) + (lane & 7);
    int b_kb  = ((lane >> 3) & 1) * 16;
    int qr = lane >> 2, qc = lane & 3;

    for (;;) {
        if (tid == 0) s_w = atomicAdd(&g_work, 1);
        __syncthreads();
        int wk = s_w;
        if (wk >= NWORK) break;
        int bb = wk / NTILE;
        int lin = wk % NTILE, ti = 0, rem = lin;
        while (rem >= NBL - ti) { rem -= NBL - ti; ti++; }
        int tj = ti + rem;
        bool isdiag = (ti == tj);
        int gi0 = ti * 128, gj0 = tj * 128;

        const __nv_bfloat16* pA = g_hl + (size_t)(bb * DD + gi0) * 2048;
        const __nv_bfloat16* pB = g_hl + (size_t)(bb * DD + gj0) * 2048;

        float acc[4][4][4];
        #pragma unroll
        for (int i = 0; i < 4; i++)
            #pragma unroll
            for (int j = 0; j < 4; j++)
                #pragma unroll
                for (int k = 0; k < 4; k++) acc[i][j][k] = 0.f;

        // preload chunks 0, 1 into stages 0, 1
        load_tile_async(pA, sb, 0, tid);
        if (!isdiag) load_tile_async(pB, sb + 16384, 0, tid);
        CP_COMMIT();
        load_tile_async(pA, sb + STAGE_BYTES, 1, tid);
        if (!isdiag) load_tile_async(pB, sb + STAGE_BYTES + 16384, 1, tid);
        CP_COMMIT();

        int slot = 0;
        for (int kc = 0; kc < NCH; kc++) {
            uint32_t cur = sb + (uint32_t)slot * STAGE_BYTES;
            CP_WAIT1();
            __syncthreads();
            if (kc + 2 < NCH) {
                int ns = slot + 2; if (ns >= 3) ns -= 3;
                uint32_t nxt = sb + (uint32_t)ns * STAGE_BYTES;
                load_tile_async(pA, nxt, kc + 2, tid);
                if (!isdiag) load_tile_async(pB, nxt + 16384, kc + 2, tid);
                CP_COMMIT();
            } else {
                CP_COMMIT();   // keep group count in lockstep
            }
            uint32_t Ab = cur;
            uint32_t Bb = isdiag ? cur : cur + 16384;
            #pragma unroll
            for (int ks = 0; ks < 2; ks++) {
                uint32_t bh[2][4], bl[2][4];
                #pragma unroll
                for (int n2 = 0; n2 < 2; n2++) {
                    uint32_t off = (uint32_t)((wc * 32 + n2 * 16 + b_row) * 128 + ks * 32 + b_kb);
                    LDSM4(bh[n2], Bb + SW128(off));
                    LDSM4(bl[n2], Bb + SW128(off + 64));
                }
                #pragma unroll
                for (int mtg = 0; mtg < 2; mtg++) {
                    uint32_t ah[2][4], al[2][4];
                    #pragma unroll
                    for (int m2 = 0; m2 < 2; m2++) {
                        int mt = mtg * 2 + m2;
                        uint32_t off = (uint32_t)((wr * 64 + mt * 16 + a_row) * 128 + ks * 32 + a_kb);
                        LDSM4(ah[m2], Ab + SW128(off));
                        LDSM4(al[m2], Ab + SW128(off + 64));
                    }
                    #pragma unroll
                    for (int m2 = 0; m2 < 2; m2++) {
                        int mt = mtg * 2 + m2;
                        #pragma unroll
                        for (int nt = 0; nt < 4; nt++) {
                            int n2 = nt >> 1, hb = (nt & 1) * 2;
                            float* c = acc[mt][nt];
                            MMA_BF16(c, ah[m2], bh[n2][hb], bh[n2][hb + 1]);
                            MMA_BF16(c, ah[m2], bl[n2][hb], bl[n2][hb + 1]);
                            MMA_BF16(c, al[m2], bh[n2][hb], bh[n2][hb + 1]);
                        }
                    }
                }
            }
            if (++slot >= 3) slot = 0;
        }
        CP_WAIT0();   // drain dummy groups

        // ---- epilogue through stage[128][132] ----
        if (tid < 128) {
            s_di[tid] = g_diag[bb * DD + gi0 + tid];
            s_dj[tid] = g_diag[bb * DD + gj0 + tid];
        }
        __syncthreads();

        float* stage = reinterpret_cast<float*>(smem);   // [128][132]
        float* dcb = g_dcov + (size_t)bb * DD * DD;

        #pragma unroll
        for (int mt = 0; mt < 4; mt++) {
            int r0 = wr * 64 + mt * 16 + qr;
            float di0 = s_di[r0], di1 = s_di[r0 + 8];
            #pragma unroll
            for (int nt = 0; nt < 4; nt++) {
                int c0 = wc * 32 + nt * 8 + qc * 2;
                float dj0 = s_dj[c0], dj1 = s_dj[c0 + 1];
                float* c = acc[mt][nt];
                stage[r0 * 132 + c0]           = sqrtf(fmaf(TEMPR, fmaxf(di0 + dj0 - 2.f * c[0], 0.f), EPSV));
                stage[r0 * 132 + c0 + 1]       = sqrtf(fmaf(TEMPR, fmaxf(di0 + dj1 - 2.f * c[1], 0.f), EPSV));
                stage[(r0 + 8) * 132 + c0]     = sqrtf(fmaf(TEMPR, fmaxf(di1 + dj0 - 2.f * c[2], 0.f), EPSV));
                stage[(r0 + 8) * 132 + c0 + 1] = sqrtf(fmaf(TEMPR, fmaxf(di1 + dj1 - 2.f * c[3], 0.f), EPSV));
            }
        }
        __syncthreads();

        // coalesced dcov store: 128 x 128
        #pragma unroll
        for (int it = 0; it < 64; it++) {
            int idx = it * 256 + tid;
            int r = idx >> 7, cjj = idx & 127;
            dcb[(size_t)(gi0 + r) * DD + gj0 + cjj] = stage[r * 132 + cjj];
        }
        // row partial sums -> slot [tj]
        #pragma unroll
        for (int rr = 0; rr < 16; rr++) {
            int r = wid * 16 + rr;
            float s = stage[r * 132 + lane] + stage[r * 132 + lane + 32] +
                      stage[r * 132 + lane + 64] + stage[r * 132 + lane + 96];
            #pragma unroll
            for (int o = 16; o > 0; o >>= 1) s += __shfl_down_sync(0xffffffffu, s, o);
            if (lane == 0) g_rspart[((size_t)bb * NBL + tj) * DD + gi0 + r] = s;
        }
        // column partial sums (mirror), off-diagonal only
        if (!isdiag && tid < 128) {
            float s = 0.f;
            #pragma unroll 8
            for (int r = 0; r < 128; r++) s += stage[r * 132 + tid];
            g_rspart[((size_t)bb * NBL + ti) * DD + gj0 + tid] = s;
        }
        __syncthreads();   // smem reuse safety for next work unit
    }
}

// ---------------------------------------------------------------------------
// Kernel 3: combine partials -> rowsum/D + tot/D^2 (deterministic)
// ---------------------------------------------------------------------------
__global__ void combine_kernel() {
    int b = blockIdx.x;
    __shared__ float sh[256];
    const float inv_d = 1.f / DD;
    float loc = 0.f;
    for (int i = threadIdx.x; i < DD; i += 256) {
        float s = 0.f;
        #pragma unroll
        for (int t = 0; t < NBL; t++) s += g_rspart[((size_t)b * NBL + t) * DD + i];
        g_rowsum[b * DD + i] = s * inv_d;
        loc += s;
    }
    sh[threadIdx.x] = loc;
    __syncthreads();
    #pragma unroll
    for (int o = 128; o > 0; o >>= 1) {
        if (threadIdx.x < o) sh[threadIdx.x] += sh[threadIdx.x + o];
        __syncthreads();
    }
    if (threadIdx.x == 0) g_tot[b] = sh[0] * (inv_d * inv_d);
}

// ---------------------------------------------------------------------------
// Kernel 4: centering + triu gather; 4 balanced row-pairs (p, 639-p) per
// block, rowsums cached in smem.
// ---------------------------------------------------------------------------
__global__ void out_kernel(float* __restrict__ out) {
    int b = blockIdx.y;
    __shared__ float srs[DD];
    for (int j = threadIdx.x; j < DD; j += 256) srs[j] = g_rowsum[b * DD + j];
    __syncthreads();
    float tot = g_tot[b];
    #pragma unroll
    for (int q = 0; q < 4; q++) {
        int p = blockIdx.x * 4 + q;
        #pragma unroll
        for (int h = 0; h < 2; h++) {
            int i = h ? (DD - 1 - p) : p;
            float si = srs[i];
            const float* dcr = g_dcov + ((size_t)b * DD + i) * DD;
            size_t base = (size_t)b * TRI + (size_t)i * DD - ((size_t)i * (i - 1)) / 2 - i;
            for (int j = i + threadIdx.x; j < DD; j += 256)
                out[base + j] = dcr[j] - si - srs[j] + tot;
        }
    }
}

// ---------------------------------------------------------------------------
extern "C" void kernel_launch(void* const* d_in, const int* in_sizes, int n_in,
                              void* d_out, int out_size) {
    const float* x = (const float*)d_in[0];
    float* out = (float*)d_out;

    cudaFuncSetAttribute(gram_mma_kernel,
                         cudaFuncAttributeMaxDynamicSharedMemorySize, SMEM_BYTES);

    conv_diag_kernel<<<(BB * DD) / 8, 256>>>(x);
    gram_mma_kernel<<<GRAM_CTAS, 256, SMEM_BYTES>>>();
    combine_kernel<<<BB, 256>>>();
    out_kernel<<<dim3(DD / 8, BB), 256>>>(out);
}